// round 7
// baseline (speedup 1.0000x reference)
#include <cuda_runtime.h>
#include <cstdint>

// ---------------- problem constants ----------------
#define VN     512          // graph nodes
#define LN     13           // sequence length
#define BB     64           // batch
#define CN     32           // in channels
#define NC     (BB*CN)      // 2048
#define MCOLS  (NC*LN)      // 26624  (= 208 * 128, exact)
#define CO     64           // out channels
#define CCAT   224          // 7*CN
#define KDIM   VN           // contraction dim of propagation

// GEMM tiling
#define BM  128
#define BNT 128
#define BK  16

// scratch: [0]=Xt, [1..3]=Y1_s, [4..6]=Y2_s, each [VN][MCOLS] row-major
__device__ float g_buf[7][(size_t)VN * MCOLS];

// ---------------- packed f32x2 helpers (Blackwell FFMA2 path) ----------------
__device__ __forceinline__ unsigned long long pack_dup(float b) {
    unsigned long long r;
    asm("mov.b64 %0, {%1, %1};" : "=l"(r) : "f"(b));
    return r;
}
__device__ __forceinline__ void fma2(unsigned long long &d,
                                     unsigned long long a,
                                     unsigned long long b) {
    asm("fma.rn.f32x2 %0, %1, %2, %0;" : "+l"(d) : "l"(a), "l"(b));
}
__device__ __forceinline__ float lo32(unsigned long long v) {
    return __uint_as_float((unsigned)(v & 0xffffffffull));
}
__device__ __forceinline__ float hi32(unsigned long long v) {
    return __uint_as_float((unsigned)(v >> 32));
}

// ---------------- 1) transpose x[n,c,v,l] -> Xt[v, nc*L + l] ----------------
__global__ void transpose_kernel(const float* __restrict__ x) {
    int v  = blockIdx.x;
    int nc = blockIdx.y * blockDim.x + threadIdx.x;
    const float* src = x + (size_t)nc * (VN * LN) + v * LN;
    float* dst = g_buf[0] + (size_t)v * MCOLS + nc * LN;
#pragma unroll
    for (int l = 0; l < LN; ++l) dst[l] = src[l];
}

// ---------------- 2) propagation SGEMM: C[w,m] = sum_v A[v,w] * B[v,m] ------
// A: support [VN,VN] row-major. B/C: [VN, MCOLS] in g_buf.
// grid: (MCOLS/BNT, VN/BM, 3), block 256. Double-buffered smem, 8x8/thread,
// inner product via fma.rn.f32x2 (2 FMAs per instruction).
__global__ void __launch_bounds__(256) prop_gemm(
    const float* __restrict__ A0, const float* __restrict__ A1,
    const float* __restrict__ A2,
    int src_base, int src_mul, int dst_base)
{
    const int z = blockIdx.z;
    const float* __restrict__ A  = (z == 0) ? A0 : ((z == 1) ? A1 : A2);
    const float* __restrict__ Bm = g_buf[src_base + z * src_mul];
    float* __restrict__       Cm = g_buf[dst_base + z];

    const int w0 = blockIdx.y * BM;
    const int m0 = blockIdx.x * BNT;

    __shared__ float As[2][BK][BM];
    __shared__ float Bs[2][BK][BNT];

    const int tid = threadIdx.x;
    const int lk = tid >> 5;   // 0..7  (k-row for loads; also handles lk+8)
    const int lq = tid & 31;   // 0..31 (float4 column for loads)
    const int ty = tid >> 4;   // 0..15 (w direction)
    const int tx = tid & 15;   // 0..15 (m direction)

    const float* Ag = A  + (size_t)lk * VN    + w0 + lq * 4;
    const float* Bg = Bm + (size_t)lk * MCOLS + m0 + lq * 4;

    unsigned long long acc[4][8];
#pragma unroll
    for (int i = 0; i < 4; ++i)
#pragma unroll
        for (int j = 0; j < 8; ++j) acc[i][j] = 0ull;

    // prologue: chunk 0 -> buffer 0
    {
        float4 a0 = *(const float4*)Ag;
        float4 a1 = *(const float4*)(Ag + 8 * VN);
        float4 b0 = *(const float4*)Bg;
        float4 b1 = *(const float4*)(Bg + 8 * MCOLS);
        *(float4*)&As[0][lk    ][lq * 4] = a0;
        *(float4*)&As[0][lk + 8][lq * 4] = a1;
        *(float4*)&Bs[0][lk    ][lq * 4] = b0;
        *(float4*)&Bs[0][lk + 8][lq * 4] = b1;
    }
    __syncthreads();

    int buf = 0;
#pragma unroll 1
    for (int kt = 0; kt < KDIM / BK; ++kt) {
        float4 na0, na1, nb0, nb1;
        const bool has_next = (kt < KDIM / BK - 1);
        if (has_next) {
            const float* Ap = Ag + (size_t)(kt + 1) * (BK * VN);
            const float* Bp = Bg + (size_t)(kt + 1) * (BK * MCOLS);
            na0 = *(const float4*)Ap;
            na1 = *(const float4*)(Ap + 8 * VN);
            nb0 = *(const float4*)Bp;
            nb1 = *(const float4*)(Bp + 8 * MCOLS);
        }
#pragma unroll
        for (int kk = 0; kk < BK; ++kk) {
            ulonglong2 alo = *(const ulonglong2*)&As[buf][kk][ty * 4];
            ulonglong2 ahi = *(const ulonglong2*)&As[buf][kk][64 + ty * 4];
            float4 blo = *(const float4*)&Bs[buf][kk][tx * 4];
            float4 bhi = *(const float4*)&Bs[buf][kk][64 + tx * 4];
            unsigned long long av[4] = {alo.x, alo.y, ahi.x, ahi.y};
            unsigned long long bb[8];
            bb[0] = pack_dup(blo.x); bb[1] = pack_dup(blo.y);
            bb[2] = pack_dup(blo.z); bb[3] = pack_dup(blo.w);
            bb[4] = pack_dup(bhi.x); bb[5] = pack_dup(bhi.y);
            bb[6] = pack_dup(bhi.z); bb[7] = pack_dup(bhi.w);
#pragma unroll
            for (int i = 0; i < 4; ++i)
#pragma unroll
                for (int j = 0; j < 8; ++j)
                    fma2(acc[i][j], av[i], bb[j]);
        }
        if (has_next) {
            int nb = buf ^ 1;
            *(float4*)&As[nb][lk    ][lq * 4] = na0;
            *(float4*)&As[nb][lk + 8][lq * 4] = na1;
            *(float4*)&Bs[nb][lk    ][lq * 4] = nb0;
            *(float4*)&Bs[nb][lk + 8][lq * 4] = nb1;
        }
        __syncthreads();
        buf ^= 1;
    }

    // epilogue writes: av[ia] lo/hi halves map to consecutive w rows
#pragma unroll
    for (int ia = 0; ia < 4; ++ia) {
        int rbase = w0 + ((ia >= 2) ? 64 : 0) + ty * 4 + (ia & 1) * 2;
        float* rowlo = Cm + (size_t)rbase * MCOLS;
        float* rowhi = rowlo + MCOLS;
        float4 vlo0 = make_float4(lo32(acc[ia][0]), lo32(acc[ia][1]),
                                  lo32(acc[ia][2]), lo32(acc[ia][3]));
        float4 vlo1 = make_float4(lo32(acc[ia][4]), lo32(acc[ia][5]),
                                  lo32(acc[ia][6]), lo32(acc[ia][7]));
        float4 vhi0 = make_float4(hi32(acc[ia][0]), hi32(acc[ia][1]),
                                  hi32(acc[ia][2]), hi32(acc[ia][3]));
        float4 vhi1 = make_float4(hi32(acc[ia][4]), hi32(acc[ia][5]),
                                  hi32(acc[ia][6]), hi32(acc[ia][7]));
        *(float4*)(rowlo + m0 + tx * 4)      = vlo0;
        *(float4*)(rowlo + m0 + 64 + tx * 4) = vlo1;
        *(float4*)(rowhi + m0 + tx * 4)      = vhi0;
        *(float4*)(rowhi + m0 + 64 + tx * 4) = vhi1;
    }
}

// ---------------- 3) epilogue: out[n,o,v,l] = b[o] + sum_k W[o,k] H_k -------
// concat order: [x, Y1_0, Y2_0, Y1_1, Y2_1, Y1_2, Y2_2]
// block = (n, 16-v tile); K chunked by 32 (= one concat block per chunk).
#define EP_VT 16
__global__ void __launch_bounds__(128) epilogue_kernel(
    const float* __restrict__ x, const float* __restrict__ Wm,
    const float* __restrict__ bias, float* __restrict__ out)
{
    const int n   = blockIdx.y;
    const int v0  = blockIdx.x * EP_VT;
    const int tid = threadIdx.x;
    const int ty  = tid >> 4;   // 0..7  -> 8 output channels each
    const int tx  = tid & 15;   // 0..15 -> one v each

    __shared__ float Ws[CN][CO];            // Ws[c][o] for current block j
    __shared__ float Hs[CN][EP_VT * LN];    // Hs[c][vi*13 + l]

    unsigned long long acc[4][LN];
#pragma unroll
    for (int p = 0; p < 4; ++p)
#pragma unroll
        for (int q = 0; q < LN; ++q) acc[p][q] = 0ull;

#pragma unroll 1
    for (int j = 0; j < 7; ++j) {
        // load W block (coalesced over k within each output row)
        for (int i = tid; i < CN * CO; i += 128) {
            int o = i >> 5, c = i & 31;
            Ws[c][o] = Wm[o * CCAT + j * CN + c];
        }
        // load H block
        if (j == 0) {
            // from x: for fixed c, (v,l) are contiguous -> 208-float runs
            const float* srcx = x + (size_t)n * (CN * VN * LN) + v0 * LN;
            for (int p = tid; p < CN * EP_VT * LN; p += 128) {
                int c = p / (EP_VT * LN);
                int r = p - c * (EP_VT * LN);
                Hs[c][r] = srcx[(size_t)c * (VN * LN) + r];
            }
        } else {
            int bufi = (j & 1) ? (1 + (j >> 1)) : (3 + (j >> 1));
            const float* src = g_buf[bufi] + (size_t)v0 * MCOLS + n * (CN * LN);
            for (int q = tid; q < EP_VT * CN * LN; q += 128) {
                int vi = q / (CN * LN);
                int r  = q - vi * (CN * LN);   // c*13 + l, contiguous in src
                int c  = r / LN;
                int l  = r - c * LN;
                Hs[c][vi * LN + l] = src[(size_t)vi * MCOLS + r];
            }
        }
        __syncthreads();
#pragma unroll 8
        for (int c = 0; c < CN; ++c) {
            ulonglong2 w01 = *(const ulonglong2*)&Ws[c][ty * 8];
            ulonglong2 w23 = *(const ulonglong2*)&Ws[c][ty * 8 + 4];
            unsigned long long wv[4] = {w01.x, w01.y, w23.x, w23.y};
            unsigned long long hb[LN];
#pragma unroll
            for (int q = 0; q < LN; ++q) hb[q] = pack_dup(Hs[c][tx * LN + q]);
#pragma unroll
            for (int p = 0; p < 4; ++p)
#pragma unroll
                for (int q = 0; q < LN; ++q)
                    fma2(acc[p][q], wv[p], hb[q]);
        }
        __syncthreads();
    }

    // write out: lo/hi halves of each acc are consecutive output channels
#pragma unroll
    for (int p = 0; p < 4; ++p) {
        int o0 = ty * 8 + p * 2;
        float blo = bias[o0], bhi = bias[o0 + 1];
        float* plo = out + ((size_t)(n * CO + o0) * VN + v0 + tx) * LN;
        float* phi = plo + (size_t)VN * LN;
#pragma unroll
        for (int q = 0; q < LN; ++q) {
            plo[q] = lo32(acc[p][q]) + blo;
            phi[q] = hi32(acc[p][q]) + bhi;
        }
    }
}

// ---------------- launch ----------------
extern "C" void kernel_launch(void* const* d_in, const int* in_sizes, int n_in,
                              void* d_out, int out_size) {
    (void)in_sizes; (void)n_in; (void)out_size;
    const float* x  = (const float*)d_in[0];
    const float* s0 = (const float*)d_in[1];
    const float* s1 = (const float*)d_in[2];
    const float* s2 = (const float*)d_in[3];
    const float* Wm = (const float*)d_in[4];
    const float* bb = (const float*)d_in[5];
    float* out = (float*)d_out;

    // 1) x -> Xt (g_buf[0])
    transpose_kernel<<<dim3(VN, NC / 128), 128>>>(x);
    // 2) order-1 propagation for all 3 supports: Y1_s = A_s^T Xt  (g_buf[1..3])
    prop_gemm<<<dim3(MCOLS / BNT, VN / BM, 3), 256>>>(s0, s1, s2, 0, 0, 1);
    //    order-2 propagation: Y2_s = A_s^T Y1_s                   (g_buf[4..6])
    prop_gemm<<<dim3(MCOLS / BNT, VN / BM, 3), 256>>>(s0, s1, s2, 1, 1, 4);
    // 3) fused concat + 1x1 conv + bias
    epilogue_kernel<<<dim3(VN / EP_VT, BB), 128>>>(x, Wm, bb, out);
}